// round 1
// baseline (speedup 1.0000x reference)
#include <cuda_runtime.h>

#define BB 2
#define SS 2048
#define EE 1024
#define HH 16
#define DD 64
#define MM (BB*SS)
#define PAD 68

// Scratch (device globals: allocation-free rule)
__device__ float g_Q[BB*HH*SS*DD];
__device__ float g_K[BB*HH*SS*DD];
__device__ float g_V[BB*HH*SS*DD];
__device__ float g_att[MM*EE];

// ---------------------------------------------------------------------------
// GEMM: C[m,n] = sum_k A[m,k] * W[n,k] + bias[n]
// A [M,1024] row-major, W [N,1024] row-major (torch Linear: x @ W.T + b)
// 128x128 tile, BK=8, 256 threads, 8x8 per thread.
// sel: 0/1/2 -> write Q/K/V in [B,H,S,D] layout;  -1 -> plain [M,N] to Cout.
// ---------------------------------------------------------------------------
__global__ __launch_bounds__(256) void gemm_bias(
    const float* __restrict__ A,
    const float* __restrict__ W,
    const float* __restrict__ bias,
    float* __restrict__ Cout,
    int sel)
{
    __shared__ float As[8*132];
    __shared__ float Bs[8*132];
    const int K = EE;

    const int tx = threadIdx.x & 15;
    const int ty = threadIdx.x >> 4;
    const int row0 = blockIdx.x * 128;
    const int col0 = blockIdx.y * 128;

    const int lr = threadIdx.x >> 1;        // 0..127
    const int lc = (threadIdx.x & 1) * 4;   // 0 or 4

    const float* Ag = A + (size_t)(row0 + lr) * K + lc;
    const float* Wg = W + (size_t)(col0 + lr) * K + lc;

    float acc[8][8];
#pragma unroll
    for (int i = 0; i < 8; i++)
#pragma unroll
        for (int j = 0; j < 8; j++) acc[i][j] = 0.f;

    for (int k0 = 0; k0 < K; k0 += 8) {
        float4 av = *(const float4*)(Ag + k0);
        float4 wv = *(const float4*)(Wg + k0);
        As[(lc+0)*132 + lr] = av.x;
        As[(lc+1)*132 + lr] = av.y;
        As[(lc+2)*132 + lr] = av.z;
        As[(lc+3)*132 + lr] = av.w;
        Bs[(lc+0)*132 + lr] = wv.x;
        Bs[(lc+1)*132 + lr] = wv.y;
        Bs[(lc+2)*132 + lr] = wv.z;
        Bs[(lc+3)*132 + lr] = wv.w;
        __syncthreads();
#pragma unroll
        for (int k = 0; k < 8; k++) {
            float4 a0 = *(const float4*)&As[k*132 + ty*8];
            float4 a1 = *(const float4*)&As[k*132 + ty*8 + 4];
            float4 b0 = *(const float4*)&Bs[k*132 + tx*8];
            float4 b1 = *(const float4*)&Bs[k*132 + tx*8 + 4];
            float ar[8] = {a0.x,a0.y,a0.z,a0.w,a1.x,a1.y,a1.z,a1.w};
            float br[8] = {b0.x,b0.y,b0.z,b0.w,b1.x,b1.y,b1.z,b1.w};
#pragma unroll
            for (int i = 0; i < 8; i++)
#pragma unroll
                for (int j = 0; j < 8; j++)
                    acc[i][j] += ar[i] * br[j];
        }
        __syncthreads();
    }

    float* outBHSD = (sel == 0) ? g_Q : (sel == 1) ? g_K : g_V;
#pragma unroll
    for (int i = 0; i < 8; i++) {
        int m = row0 + ty*8 + i;
#pragma unroll
        for (int j = 0; j < 8; j++) {
            int n = col0 + tx*8 + j;
            float v = acc[i][j] + bias[n];
            if (sel < 0) {
                Cout[(size_t)m*EE + n] = v;
            } else {
                int b = m >> 11;      // m / 2048
                int s = m & 2047;
                int h = n >> 6;       // n / 64
                int d = n & 63;
                outBHSD[(((size_t)b*HH + h)*SS + s)*DD + d] = v;
            }
        }
    }
}

// ---------------------------------------------------------------------------
// Flash attention (fp32, online softmax).
// grid: (S/64, B*H). 64-query x 64-key tiles. 256 threads, 4x4 per thread.
// Writes attention output to g_att in [B,S,H*D] = [M,E] layout.
// ---------------------------------------------------------------------------
__global__ __launch_bounds__(256) void attn_kernel()
{
    extern __shared__ float sm[];
    float* Qs = sm;                 // 64 * PAD
    float* Ks = Qs + 64*PAD;
    float* Vs = Ks + 64*PAD;
    float* Ps = Vs + 64*PAD;

    const int bh = blockIdx.y;      // b*H + h, 0..31
    const int qb = blockIdx.x;      // query tile, 0..31
    const int t  = threadIdx.x;
    const int tx = t & 15;
    const int ty = t >> 4;

    const float scale = 0.125f;     // 1/sqrt(64)
    const float* Qg = g_Q + ((size_t)bh*SS + qb*64)*DD;

    // Load Q tile (scaled). 64 rows x 64 cols; PAD=68 keeps float4 alignment.
    for (int idx = t; idx < 64*16; idx += 256) {
        int r = idx >> 4;
        int c = (idx & 15) * 4;
        float4 v = *(const float4*)(Qg + r*DD + c);
        v.x *= scale; v.y *= scale; v.z *= scale; v.w *= scale;
        *(float4*)&Qs[r*PAD + c] = v;
    }

    float m_i[4], l_i[4], o[4][4];
#pragma unroll
    for (int i = 0; i < 4; i++) {
        m_i[i] = -1e30f; l_i[i] = 0.f;
#pragma unroll
        for (int j = 0; j < 4; j++) o[i][j] = 0.f;
    }
    __syncthreads();

    for (int kb = 0; kb < SS/64; kb++) {
        const float* Kg = g_K + ((size_t)bh*SS + kb*64)*DD;
        const float* Vg = g_V + ((size_t)bh*SS + kb*64)*DD;
        for (int idx = t; idx < 64*16; idx += 256) {
            int r = idx >> 4;
            int c = (idx & 15) * 4;
            *(float4*)&Ks[r*PAD + c] = *(const float4*)(Kg + r*DD + c);
            *(float4*)&Vs[r*PAD + c] = *(const float4*)(Vg + r*DD + c);
        }
        __syncthreads();

        // S = Qs @ Ks^T  (this thread: rows 4ty.., cols 4tx..)
        float s[4][4];
#pragma unroll
        for (int i = 0; i < 4; i++)
#pragma unroll
            for (int j = 0; j < 4; j++) s[i][j] = 0.f;

#pragma unroll
        for (int k = 0; k < DD; k += 4) {
            float4 q[4], kk[4];
#pragma unroll
            for (int i = 0; i < 4; i++) q[i]  = *(const float4*)&Qs[(ty*4+i)*PAD + k];
#pragma unroll
            for (int j = 0; j < 4; j++) kk[j] = *(const float4*)&Ks[(tx*4+j)*PAD + k];
#pragma unroll
            for (int i = 0; i < 4; i++)
#pragma unroll
                for (int j = 0; j < 4; j++)
                    s[i][j] += q[i].x*kk[j].x + q[i].y*kk[j].y
                             + q[i].z*kk[j].z + q[i].w*kk[j].w;
        }

        // Online softmax update (row stats reduced over the 16 tx lanes).
#pragma unroll
        for (int i = 0; i < 4; i++) {
            float rm = fmaxf(fmaxf(s[i][0], s[i][1]), fmaxf(s[i][2], s[i][3]));
#pragma unroll
            for (int off = 8; off >= 1; off >>= 1)
                rm = fmaxf(rm, __shfl_xor_sync(0xffffffffu, rm, off));
            float mnew = fmaxf(m_i[i], rm);

            float sum = 0.f;
#pragma unroll
            for (int j = 0; j < 4; j++) { s[i][j] = __expf(s[i][j] - mnew); sum += s[i][j]; }
#pragma unroll
            for (int off = 8; off >= 1; off >>= 1)
                sum += __shfl_xor_sync(0xffffffffu, sum, off);

            float alpha = __expf(m_i[i] - mnew);
            l_i[i] = l_i[i]*alpha + sum;
            m_i[i] = mnew;
#pragma unroll
            for (int j = 0; j < 4; j++) {
                o[i][j] *= alpha;
                Ps[(ty*4+i)*PAD + tx*4+j] = s[i][j];
            }
        }
        __syncthreads();

        // O += P @ V
#pragma unroll
        for (int c0 = 0; c0 < 64; c0 += 4) {
            float4 p[4];
#pragma unroll
            for (int i = 0; i < 4; i++) p[i] = *(const float4*)&Ps[(ty*4+i)*PAD + c0];
#pragma unroll
            for (int cc = 0; cc < 4; cc++) {
                float4 v = *(const float4*)&Vs[(c0+cc)*PAD + tx*4];
#pragma unroll
                for (int i = 0; i < 4; i++) {
                    float pv = (cc == 0) ? p[i].x : (cc == 1) ? p[i].y
                             : (cc == 2) ? p[i].z : p[i].w;
                    o[i][0] += pv * v.x;
                    o[i][1] += pv * v.y;
                    o[i][2] += pv * v.z;
                    o[i][3] += pv * v.w;
                }
            }
        }
        __syncthreads();
    }

    // Normalize and write to g_att in [B, S, H*D] layout
    const int b = bh >> 4;
    const int h = bh & 15;
#pragma unroll
    for (int i = 0; i < 4; i++) {
        float inv = 1.f / l_i[i];
        int srow = qb*64 + ty*4 + i;
        float4 v = make_float4(o[i][0]*inv, o[i][1]*inv, o[i][2]*inv, o[i][3]*inv);
        *(float4*)&g_att[((size_t)b*SS + srow)*EE + h*DD + tx*4] = v;
    }
}

// ---------------------------------------------------------------------------
extern "C" void kernel_launch(void* const* d_in, const int* in_sizes, int n_in,
                              void* d_out, int out_size)
{
    const float* x  = (const float*)d_in[0];
    const float* Wq = (const float*)d_in[1];
    const float* bq = (const float*)d_in[2];
    const float* Wk = (const float*)d_in[3];
    const float* bk = (const float*)d_in[4];
    const float* Wv = (const float*)d_in[5];
    const float* bv = (const float*)d_in[6];
    const float* Wo = (const float*)d_in[7];
    const float* bo = (const float*)d_in[8];
    float* out = (float*)d_out;

    dim3 gp(MM/128, EE/128);
    gemm_bias<<<gp, 256>>>(x, Wq, bq, nullptr, 0);
    gemm_bias<<<gp, 256>>>(x, Wk, bk, nullptr, 1);
    gemm_bias<<<gp, 256>>>(x, Wv, bv, nullptr, 2);

    size_t smem = (size_t)4 * 64 * PAD * sizeof(float);   // 69,632 B
    cudaFuncSetAttribute(attn_kernel, cudaFuncAttributeMaxDynamicSharedMemorySize,
                         (int)smem);
    attn_kernel<<<dim3(SS/64, BB*HH), 256, smem>>>();

    float* attp = nullptr;
    cudaGetSymbolAddress((void**)&attp, g_att);
    gemm_bias<<<gp, 256>>>(attp, Wo, bo, out, -1);
}